// round 3
// baseline (speedup 1.0000x reference)
#include <cuda_runtime.h>

// Problem shape (fixed by reference): B=64, M=64, P=128, V=32.
// Output = 0.5 * min over (m,p) of point-polygon distance, BATCH 63 ONLY.
#define BN 64
#define MN 64
#define PN 128
#define VN 32
#define EPSF 1e-12f

// Cross-block reduction scratch (allocation-free: __device__ globals).
__device__ float        g_blockmin[PN];
__device__ unsigned int g_count = 0;   // self-resetting: last block writes 0

__global__ void __launch_bounds__(MN)
pl_kernel(const float* __restrict__ last_point,
          const float* __restrict__ polygon_coords,
          float* __restrict__ out) {
    __shared__ float2 s_a[VN];
    __shared__ float2 s_b[VN];
    __shared__ float  s_inv2[VN];    // 1 / (|ab|^2 + eps)
    __shared__ float  s_invdy[VN];   // 1 / (by - ay + eps)
    __shared__ float  s_warpmin[MN / 32];
    __shared__ int    s_last;

    const int p = blockIdx.x;
    const int t = threadIdx.x;

    // Hoist the point load so its latency overlaps the edge-table build.
    const float2 pt = reinterpret_cast<const float2*>(last_point)[(BN - 1) * MN + t];
    const float px = pt.x;
    const float py = pt.y;

    // Polygon p of batch 63: vertices are contiguous float2.
    const float2* pc = reinterpret_cast<const float2*>(polygon_coords)
                       + (((BN - 1) * PN + p) * VN);

    if (t < VN) {
        float2 a = pc[t];
        float2 b = pc[(t + 1) & (VN - 1)];   // roll(-1) over vertex axis
        s_a[t] = a;
        s_b[t] = b;
        float abx = b.x - a.x;
        float aby = b.y - a.y;
        s_inv2[t]  = 1.0f / (abx * abx + aby * aby + EPSF);
        s_invdy[t] = 1.0f / (aby + EPSF);
    }
    __syncthreads();

    float mindd = 3.402823466e+38f;
    int crossings = 0;

#pragma unroll
    for (int v = 0; v < VN; ++v) {
        const float2 a = s_a[v];
        const float2 b = s_b[v];
        const float abx = b.x - a.x;
        const float aby = b.y - a.y;
        const float apx = px - a.x;
        const float apy = py - a.y;

        // Squared segment distance (sqrt deferred — monotone).
        float tt = (apx * abx + apy * aby) * s_inv2[v];
        tt = fminf(fmaxf(tt, 0.0f), 1.0f);
        const float dx = apx - tt * abx;
        const float dy = apy - tt * aby;
        const float dd = dx * dx + dy * dy;
        mindd = fminf(mindd, dd);

        // Ray-crossing (even-odd) test.
        const bool straddles = (a.y > py) != (b.y > py);
        const float x_int = a.x + abx * (py - a.y) * s_invdy[v];
        if (straddles && (px < x_int)) ++crossings;
    }

    const bool inside = (crossings & 1) != 0;
    float val = inside ? 0.0f : sqrtf(fmaxf(mindd, EPSF));

    // Warp min via single redux (val >= 0 -> IEEE bit order == numeric order).
    unsigned uv = __reduce_min_sync(0xFFFFFFFFu, __float_as_uint(val));
    if ((t & 31) == 0) s_warpmin[t >> 5] = __uint_as_float(uv);
    __syncthreads();

    if (t == 0) {
        float m = fminf(s_warpmin[0], s_warpmin[1]);
        g_blockmin[p] = m;               // plain store, no atomic contention
        __threadfence();
        unsigned old = atomicAdd(&g_count, 1u);
        s_last = (old == PN - 1) ? 1 : 0;
    }
    __syncthreads();

    // Last block to finish performs the final 128-way reduction + writes out.
    if (s_last) {
        __threadfence();                 // acquire: make all g_blockmin visible
        float m = fminf(g_blockmin[t], g_blockmin[t + MN]);
        unsigned um = __reduce_min_sync(0xFFFFFFFFu, __float_as_uint(m));
        if ((t & 31) == 0) s_warpmin[t >> 5] = __uint_as_float(um);
        __syncthreads();
        if (t == 0) {
            out[0] = 0.5f * fminf(s_warpmin[0], s_warpmin[1]);
            g_count = 0;                 // self-reset -> deterministic replays
        }
    }
}

extern "C" void kernel_launch(void* const* d_in, const int* in_sizes, int n_in,
                              void* d_out, int out_size) {
    const float* last_point     = (const float*)d_in[0];  // [64, 64, 2] f32
    const float* polygon_coords = (const float*)d_in[1];  // [64, 128, 32, 2] f32
    float* out = (float*)d_out;                           // scalar f32 output

    pl_kernel<<<PN, MN>>>(last_point, polygon_coords, out);
}

// round 4
// speedup vs baseline: 1.2891x; 1.2891x over previous
#include <cuda_runtime.h>

// Problem shape (fixed by reference): B=64, M=64, P=128, V=32.
// Output = 0.5 * min over (m,p) of point-polygon distance, BATCH 63 ONLY.
#define BN 64
#define MN 64
#define PN 128
#define VN 32
#define EPSF 1e-12f

// Per-block minima (squared distance, or exact 0 if a point is inside).
// Plain stores to distinct slots — no same-address atomic serialization.
__device__ float g_blockmin[PN];

__global__ void __launch_bounds__(MN)
pl_main(const float* __restrict__ last_point,
        const float* __restrict__ polygon_coords) {
    // Edge tables packed for 2x LDS.128 per edge (broadcast reads, conflict-free).
    __shared__ float4 s_e0[VN];   // { ax, ay, abx, aby }
    __shared__ float4 s_e1[VN];   // { inv2, invdy, by, - }
    __shared__ float  s_warpmin[MN / 32];

    const int p = blockIdx.x;
    const int t = threadIdx.x;

    // Hoist point load: last_point[63, t, :] (latency overlaps edge-table build).
    const float2 pt = reinterpret_cast<const float2*>(last_point)[(BN - 1) * MN + t];
    const float px = pt.x;
    const float py = pt.y;

    // Polygon p of batch 63: vertices are contiguous float2.
    const float2* pc = reinterpret_cast<const float2*>(polygon_coords)
                       + (((BN - 1) * PN + p) * VN);

    if (t < VN) {
        const float2 a = pc[t];
        const float2 b = pc[(t + 1) & (VN - 1)];   // roll(-1) over vertex axis
        const float abx = b.x - a.x;
        const float aby = b.y - a.y;
        s_e0[t] = make_float4(a.x, a.y, abx, aby);
        s_e1[t] = make_float4(1.0f / (abx * abx + aby * aby + EPSF),
                              1.0f / (aby + EPSF),
                              b.y, 0.0f);
    }
    __syncthreads();

    float mindd = 3.402823466e+38f;
    int crossings = 0;

#pragma unroll
    for (int v = 0; v < VN; ++v) {
        const float4 e0 = s_e0[v];   // ax, ay, abx, aby
        const float4 e1 = s_e1[v];   // inv2, invdy, by
        const float apx = px - e0.x;
        const float apy = py - e0.y;

        // Squared segment distance (sqrt deferred to finalize — monotone).
        float tt = (apx * e0.z + apy * e0.w) * e1.x;
        tt = fminf(fmaxf(tt, 0.0f), 1.0f);
        const float dx = apx - tt * e0.z;
        const float dy = apy - tt * e0.w;
        mindd = fminf(mindd, dx * dx + dy * dy);

        // Ray-crossing (even-odd) test.
        const bool straddles = (e0.y > py) != (e1.z > py);
        const float x_int = e0.x + e0.z * (py - e0.y) * e1.y;
        if (straddles && (px < x_int)) ++crossings;
    }

    // Candidate: exact 0 if inside (matches jnp.where), else max(mindd, EPS)
    // so the deferred sqrt reproduces sqrt(maximum(dd, EPS)) exactly.
    const float cand = ((crossings & 1) != 0) ? 0.0f : fmaxf(mindd, EPSF);

    // Block min: single redux per warp (all candidates >= 0 -> bit order == numeric).
    const unsigned uv = __reduce_min_sync(0xFFFFFFFFu, __float_as_uint(cand));
    if ((t & 31) == 0) s_warpmin[t >> 5] = __uint_as_float(uv);
    __syncthreads();

    if (t == 0)
        g_blockmin[p] = fminf(s_warpmin[0], s_warpmin[1]);  // plain STG, distinct slot
}

__global__ void __launch_bounds__(PN)
pl_final(float* __restrict__ out) {
    __shared__ float s_warpmin[PN / 32];
    const int t = threadIdx.x;

    const float v = g_blockmin[t];
    const unsigned uv = __reduce_min_sync(0xFFFFFFFFu, __float_as_uint(v));
    if ((t & 31) == 0) s_warpmin[t >> 5] = __uint_as_float(uv);
    __syncthreads();

    if (t == 0) {
        float m = fminf(fminf(s_warpmin[0], s_warpmin[1]),
                        fminf(s_warpmin[2], s_warpmin[3]));
        out[0] = 0.5f * sqrtf(m);   // sqrt(0) == 0 keeps inside-case exact
    }
}

extern "C" void kernel_launch(void* const* d_in, const int* in_sizes, int n_in,
                              void* d_out, int out_size) {
    const float* last_point     = (const float*)d_in[0];  // [64, 64, 2] f32
    const float* polygon_coords = (const float*)d_in[1];  // [64, 128, 32, 2] f32
    float* out = (float*)d_out;                           // scalar f32 output

    pl_main<<<PN, MN>>>(last_point, polygon_coords);
    pl_final<<<1, PN>>>(out);
}